// round 1
// baseline (speedup 1.0000x reference)
#include <cuda_runtime.h>
#include <math.h>
#include <stdint.h>

// ---------------------------------------------------------------------------
// Problem constants
// ---------------------------------------------------------------------------
#define B_SZ   8
#define C_IN   64
#define HID    256
#define H_SZ   256
#define W_SZ   256
#define P_WIN  4

// Tile: 4 rows x 32 cols = 128 pixels per CTA
#define TROWS  4
#define TCOLS  32
#define TPIX   128
#define THREADS 512

// smem pitches (floats), padded to avoid bank conflicts while keeping 16B align
#define W1_PITCH 260   // w1_s[c][hid], c=0..63, hid=0..255
#define W2_PITCH 68    // w2_s[hid][c], hid=0..255, c=0..63
#define X_PITCH  132   // x_s[c][pix]
#define H_PITCH  132   // h_s[hidc][pix], hidc=0..31

// smem layout (byte offsets)
#define OFF_W1 0
#define SZ_W1  (64 * W1_PITCH * 4)            // 66560
#define OFF_W2 (OFF_W1 + SZ_W1)               // 66560
#define SZ_W2  (256 * W2_PITCH * 4)           // 69632
#define OFF_X  (OFF_W2 + SZ_W2)               // 136192
#define SZ_X   (64 * X_PITCH * 4)             // 33792
#define OFF_H  (OFF_X + SZ_X)                 // 169984
#define SZ_H   (32 * H_PITCH * 4)             // 16896
#define OFF_B1 (OFF_H + SZ_H)                 // 186880
#define OFF_B2 (OFF_B1 + 256 * 4)             // 187904
#define SMEM_BYTES (OFF_B2 + 64 * 4)          // 188160

// ---------------------------------------------------------------------------
// Per-channel 16x16 Fourier-mix matrix, precomputed each launch.
// out_patch = M_c @ in_patch, where patch index = row*4 + col.
// ---------------------------------------------------------------------------
__device__ float g_M[64 * 256];

__global__ void build_mix_kernel(const float* __restrict__ cw) {
    // cw layout: [P=4][P/2+1=3][C=64][2]
    const int c   = blockIdx.x;      // 0..63
    const int t   = threadIdx.x;     // 0..255
    const int in  = t >> 4;          // s*4 + tt
    const int out = t & 15;          // p*4 + q
    const int s  = in >> 2, tt = in & 3;
    const int p  = out >> 2, q  = out & 3;

    // e^{i * idx * pi/2} = (cs[idx], sn[idx]) -- exact for P=4
    const float cs[4] = {1.f, 0.f, -1.f, 0.f};
    const float sn[4] = {0.f, 1.f, 0.f, -1.f};

    float tre[3] = {0.f, 0.f, 0.f};
    float tim[3] = {0.f, 0.f, 0.f};

    #pragma unroll
    for (int u = 0; u < 4; ++u) {
        const int e2 = (u * p) & 3;          // e^{+2pi i u p / 4}
        const float c2 = cs[e2], s2 = sn[e2];
        #pragma unroll
        for (int v = 0; v < 3; ++v) {
            const int e1 = (4 - ((u * s + v * tt) & 3)) & 3;  // e^{-2pi i (us+vt)/4}
            const float yr = 0.25f * cs[e1];
            const float yi = 0.25f * sn[e1];
            const float wr = cw[((u * 3 + v) * 64 + c) * 2 + 0];
            const float wi = cw[((u * 3 + v) * 64 + c) * 2 + 1];
            const float zr = yr * wr - yi * wi;
            const float zi = yr * wi + yi * wr;
            tre[v] += zr * c2 - zi * s2;
            tim[v] += zr * s2 + zi * c2;
        }
    }

    // irfft along last axis (ortho), numpy convention:
    // imag parts of DC (v=0) and Nyquist (v=2) bins are discarded.
    const float sgn = (q & 1) ? -1.f : 1.f;                 // (-1)^q
    const float val = 0.25f * (tre[0] + sgn * tre[2]
                               + 2.f * (tre[1] * cs[q] - tim[1] * sn[q]));
    g_M[c * 256 + out * 16 + in] = val;
}

// ---------------------------------------------------------------------------
// Main fused kernel: FFN (GEMM1 -> exact GELU -> GEMM2) + Fourier window mix
// ---------------------------------------------------------------------------
__device__ __forceinline__ float gelu_exact(float x) {
    return 0.5f * x * (1.f + erff(x * 0.70710678118654752440f));
}

__global__ __launch_bounds__(THREADS, 1)
void fmffn_kernel(const float* __restrict__ x,
                  const float* __restrict__ w1,
                  const float* __restrict__ b1,
                  const float* __restrict__ w2,
                  const float* __restrict__ b2,
                  float* __restrict__ out) {
    extern __shared__ float smem[];
    float* w1_s = smem + OFF_W1 / 4;
    float* w2_s = smem + OFF_W2 / 4;
    float* x_s  = smem + OFF_X  / 4;
    float* h_s  = smem + OFF_H  / 4;
    float* b1_s = smem + OFF_B1 / 4;
    float* b2_s = smem + OFF_B2 / 4;

    const int tid = threadIdx.x;
    const int tx  = tid & 31;   // pixel group: pixels 4*tx .. 4*tx+3
    const int ty  = tid >> 5;   // 0..15
    const int b   = blockIdx.z;
    const int h0  = blockIdx.y * TROWS;
    const int w0  = blockIdx.x * TCOLS;

    // ---- cooperative loads ----
    // w1 global [HID][C] -> w1_s[c][hid]
    for (int i = tid; i < HID * C_IN; i += THREADS) {
        const int hid = i >> 6, c = i & 63;
        w1_s[c * W1_PITCH + hid] = w1[i];
    }
    // w2 global [C][HID] -> w2_s[hid][c]
    for (int i = tid; i < C_IN * HID; i += THREADS) {
        const int c = i >> 8, hid = i & 255;
        w2_s[hid * W2_PITCH + c] = w2[i];
    }
    // x tile -> x_s[c][pix], pix = r*32 + col
    for (int i = tid; i < C_IN * TPIX; i += THREADS) {
        const int c = i >> 7, pix = i & 127;
        const int r = pix >> 5, col = pix & 31;
        x_s[c * X_PITCH + pix] =
            x[(((size_t)b * C_IN + c) * H_SZ + (h0 + r)) * W_SZ + (w0 + col)];
    }
    if (tid < HID)  b1_s[tid] = b1[tid];
    if (tid < C_IN) b2_s[tid] = b2[tid];
    __syncthreads();

    // ---- persistent accumulators: y[c][pix], thread owns 4 c x 4 pix ----
    float acc2[4][4];
    #pragma unroll
    for (int i = 0; i < 4; ++i) {
        const float bv = b2_s[ty * 4 + i];
        #pragma unroll
        for (int j = 0; j < 4; ++j) acc2[i][j] = bv;
    }

    // ---- hid chunks of 32 ----
    for (int ch = 0; ch < 8; ++ch) {
        const int hid0 = ch * 32;

        // GEMM1: h[hid0 + ty*2 + i][4*tx + j] over k = 0..63 (c)
        float acc1[2][4] = {};
        const float* wp = &w1_s[hid0 + ty * 2];
        const float* xp = &x_s[tx * 4];
        #pragma unroll 8
        for (int k = 0; k < 64; ++k) {
            const float2 wv = *(const float2*)(wp + k * W1_PITCH);
            const float4 xv = *(const float4*)(xp + k * X_PITCH);
            acc1[0][0] += wv.x * xv.x; acc1[0][1] += wv.x * xv.y;
            acc1[0][2] += wv.x * xv.z; acc1[0][3] += wv.x * xv.w;
            acc1[1][0] += wv.y * xv.x; acc1[1][1] += wv.y * xv.y;
            acc1[1][2] += wv.y * xv.z; acc1[1][3] += wv.y * xv.w;
        }

        __syncthreads();   // previous chunk's GEMM2 reads of h_s are done
        #pragma unroll
        for (int i = 0; i < 2; ++i) {
            const float bb = b1_s[hid0 + ty * 2 + i];
            float4 g;
            g.x = gelu_exact(acc1[i][0] + bb);
            g.y = gelu_exact(acc1[i][1] + bb);
            g.z = gelu_exact(acc1[i][2] + bb);
            g.w = gelu_exact(acc1[i][3] + bb);
            *(float4*)&h_s[(ty * 2 + i) * H_PITCH + tx * 4] = g;
        }
        __syncthreads();

        // GEMM2: y[ty*4 + i][4*tx + j] += w2[c][hid] * h[hid][pix], k = 0..31
        const float* hp  = &h_s[tx * 4];
        const float* w2p = &w2_s[hid0 * W2_PITCH + ty * 4];
        #pragma unroll 8
        for (int k = 0; k < 32; ++k) {
            const float4 hv = *(const float4*)(hp + k * H_PITCH);
            const float4 wv = *(const float4*)(w2p + k * W2_PITCH);
            acc2[0][0] += wv.x * hv.x; acc2[0][1] += wv.x * hv.y;
            acc2[0][2] += wv.x * hv.z; acc2[0][3] += wv.x * hv.w;
            acc2[1][0] += wv.y * hv.x; acc2[1][1] += wv.y * hv.y;
            acc2[1][2] += wv.y * hv.z; acc2[1][3] += wv.y * hv.w;
            acc2[2][0] += wv.z * hv.x; acc2[2][1] += wv.z * hv.y;
            acc2[2][2] += wv.z * hv.z; acc2[2][3] += wv.z * hv.w;
            acc2[3][0] += wv.w * hv.x; acc2[3][1] += wv.w * hv.y;
            acc2[3][2] += wv.w * hv.z; acc2[3][3] += wv.w * hv.w;
        }
    }

    __syncthreads();  // done with x_s (reused as y_s) and w1_s (reused as m_s)

    // ---- stage y tile + mix matrices into smem ----
    float* y_s = x_s;   // [64][X_PITCH]
    float* m_s = w1_s;  // flat [64*256]
    #pragma unroll
    for (int i = 0; i < 4; ++i) {
        float4 v;
        v.x = acc2[i][0]; v.y = acc2[i][1]; v.z = acc2[i][2]; v.w = acc2[i][3];
        *(float4*)&y_s[(ty * 4 + i) * X_PITCH + tx * 4] = v;
    }
    for (int i = tid; i < 64 * 256; i += THREADS) m_s[i] = g_M[i];
    __syncthreads();

    // ---- Fourier mix: one 4x4 window per thread ----
    const int c  = tid >> 3;   // channel 0..63
    const int wc = tid & 7;    // window col 0..7

    float pin[16];
    #pragma unroll
    for (int r = 0; r < 4; ++r) {
        const float4 v = *(const float4*)&y_s[c * X_PITCH + r * 32 + wc * 4];
        pin[r * 4 + 0] = v.x; pin[r * 4 + 1] = v.y;
        pin[r * 4 + 2] = v.z; pin[r * 4 + 3] = v.w;
    }

    float po[16];
    const float* mrow = &m_s[c * 256];
    #pragma unroll
    for (int o = 0; o < 16; ++o) {
        float s = 0.f;
        #pragma unroll
        for (int i4 = 0; i4 < 4; ++i4) {
            const float4 mv = *(const float4*)&mrow[o * 16 + i4 * 4];
            s += mv.x * pin[i4 * 4 + 0];
            s += mv.y * pin[i4 * 4 + 1];
            s += mv.z * pin[i4 * 4 + 2];
            s += mv.w * pin[i4 * 4 + 3];
        }
        po[o] = s;
    }

    const size_t obase = (((size_t)b * C_IN + c) * H_SZ + h0) * W_SZ + w0 + wc * 4;
    #pragma unroll
    for (int r = 0; r < 4; ++r) {
        float4 v;
        v.x = po[r * 4 + 0]; v.y = po[r * 4 + 1];
        v.z = po[r * 4 + 2]; v.w = po[r * 4 + 3];
        *(float4*)&out[obase + (size_t)r * W_SZ] = v;
    }
}

// ---------------------------------------------------------------------------
// Launch
// ---------------------------------------------------------------------------
extern "C" void kernel_launch(void* const* d_in, const int* in_sizes, int n_in,
                              void* d_out, int out_size) {
    const float* x  = (const float*)d_in[0];
    const float* w1 = (const float*)d_in[1];
    const float* b1 = (const float*)d_in[2];
    const float* w2 = (const float*)d_in[3];
    const float* b2 = (const float*)d_in[4];
    const float* cw = (const float*)d_in[5];
    float* out = (float*)d_out;

    cudaFuncSetAttribute(fmffn_kernel,
                         cudaFuncAttributeMaxDynamicSharedMemorySize, SMEM_BYTES);

    build_mix_kernel<<<64, 256>>>(cw);

    dim3 grid(W_SZ / TCOLS, H_SZ / TROWS, B_SZ);  // (8, 64, 8)
    fmffn_kernel<<<grid, THREADS, SMEM_BYTES>>>(x, w1, b1, w2, b2, out);
}